// round 1
// baseline (speedup 1.0000x reference)
#include <cuda_runtime.h>

// Problem constants (fixed by the reference)
#define BATCH 64
#define NPTS  8192
#define SGRID 384
#define OUTD  128
#define BLKS_PER_BATCH (NPTS / 256)   // 32

// Scratch (static __device__ arrays — no allocations allowed)
__device__ int      d_offmin[BATCH * 2];        // per-batch min of coord (2 dims)
__device__ unsigned d_gpack [BATCH * NPTS];     // packed (g0+1024)|(g1+1024)<<16

// ---------------------------------------------------------------------------
// Kernel 1: per-point lattice math, per-batch coordinate-min reduction,
// store packed greedy coords for the scatter pass.
// ---------------------------------------------------------------------------
__global__ void __launch_bounds__(256) k_compute(const float* __restrict__ pc1,
                                                 const float* __restrict__ tmat)
{
    const int b = blockIdx.x >> 5;                       // 32 blocks per batch
    const int n = ((blockIdx.x & 31) << 8) + threadIdx.x;

    __shared__ float M[9];
    if (threadIdx.x < 9) M[threadIdx.x] = tmat[b * 9 + threadIdx.x];
    __syncthreads();

    const float* p = pc1 + (size_t)b * 3 * NPTS + n;
    const float p0 = p[0], p1 = p[NPTS], p2 = p[2 * NPTS];

    // elevated = M @ p
    const float e0 = M[0] * p0 + M[1] * p1 + M[2] * p2;
    const float e1 = M[3] * p0 + M[4] * p1 + M[5] * p2;
    const float e2 = M[6] * p0 + M[7] * p1 + M[8] * p2;

    // greedy = round(e/3)*3  (IEEE divide + round-half-even, matching jnp)
    const float q0 = rintf(__fdiv_rn(e0, 3.0f));
    const float q1 = rintf(__fdiv_rn(e1, 3.0f));
    const float q2 = rintf(__fdiv_rn(e2, 3.0f));
    const float d0 = e0 - 3.0f * q0;
    const float d1 = e1 - 3.0f * q1;
    const float d2 = e2 - 3.0f * q2;

    const int i0 = (int)q0, i1 = (int)q1, i2 = (int)q2;
    const int rs = i0 + i1 + i2;                // remainder_sum (exact int)

    // rank = inverse of stable descending argsort of (d0,d1,d2)
    int rk0 = (d1 > d0) + (d2 > d0);
    int rk1 = (d0 > d1) + (d2 > d1) + (d0 == d1);
    // rk2 never feeds coords 0/1; not needed downstream.

    int g0 = 3 * i0;
    int g1 = 3 * i1;

    int sh0 = 0, sh1 = 0;
    if (rs > 0) {
        const int thr = 3 - rs;
        sh0 = (rk0 >= thr) ? -3 : 0;
        sh1 = (rk1 >= thr) ? -3 : 0;
    } else if (rs < 0) {
        sh0 = (rk0 < -rs) ? 3 : 0;
        sh1 = (rk1 < -rs) ? 3 : 0;
    }
    g0 += sh0;  g1 += sh1;
    rk0 += sh0 + rs;
    rk1 += sh1 + rs;

    // JAX gather semantics for CANONICAL[rank]: wrap negatives by +3, clamp [0,2]
    int cr0 = (rk0 < 0) ? rk0 + 3 : rk0;  cr0 = min(max(cr0, 0), 2);
    int cr1 = (rk1 < 0) ? rk1 + 3 : rk1;  cr1 = min(max(cr1, 0), 2);

    // min over r of CANONICAL[cr][r] == -cr  => per-point coord min candidate
    int m0 = g0 - cr0;
    int m1 = g1 - cr1;

    d_gpack[b * NPTS + n] = (unsigned)(g0 + 1024) | ((unsigned)(g1 + 1024) << 16);

    // block min-reduction -> 1 atomicMin per coord per block
    #pragma unroll
    for (int o = 16; o; o >>= 1) {
        m0 = min(m0, __shfl_xor_sync(0xFFFFFFFFu, m0, o));
        m1 = min(m1, __shfl_xor_sync(0xFFFFFFFFu, m1, o));
    }
    __shared__ int s0[8], s1[8];
    if ((threadIdx.x & 31) == 0) {
        s0[threadIdx.x >> 5] = m0;
        s1[threadIdx.x >> 5] = m1;
    }
    __syncthreads();
    if (threadIdx.x == 0) {
        int a = s0[0], c = s1[0];
        #pragma unroll
        for (int w = 1; w < 8; w++) { a = min(a, s0[w]); c = min(c, s1[w]); }
        atomicMin(&d_offmin[b * 2 + 0], a);
        atomicMin(&d_offmin[b * 2 + 1], c);
    }
}

// ---------------------------------------------------------------------------
// Kernel 2: scatter-add features into the 128x128x3 output.
// The r=0 simplex coord is exactly greedy (multiple of 3), so after offset
// subtraction it lands on the picked sub-grid: out cell = (row/3, col/3).
// ---------------------------------------------------------------------------
__global__ void __launch_bounds__(256) k_scatter(const float* __restrict__ feat,
                                                 float* __restrict__ out)
{
    const int b = blockIdx.x >> 5;
    const int n = ((blockIdx.x & 31) << 8) + threadIdx.x;

    const unsigned pk = d_gpack[b * NPTS + n];
    const int g0 = (int)(pk & 0xFFFFu) - 1024;
    const int g1 = (int)(pk >> 16)     - 1024;

    const int off0 = __ldg(&d_offmin[b * 2 + 0]);
    const int off1 = __ldg(&d_offmin[b * 2 + 1]);

    const int row = g0 - off0;          // >= 0 by construction (offset is min)
    const int col = g1 - off1;
    if (row < SGRID && col < SGRID) {
        const int u = row / 3;          // row ≡ pts_pick0 (mod 3) exactly
        const int v = col / 3;
        const float* f = feat + (size_t)b * 3 * NPTS + n;
        float* o = out + (((size_t)(b * OUTD + u) * OUTD + v) * 3);
        atomicAdd(o + 0, f[0]);
        atomicAdd(o + 1, f[NPTS]);
        atomicAdd(o + 2, f[2 * NPTS]);
    }
}

// ---------------------------------------------------------------------------
extern "C" void kernel_launch(void* const* d_in, const int* in_sizes, int n_in,
                              void* d_out, int out_size)
{
    const float* pc1  = (const float*)d_in[0];
    const float* feat = (const float*)d_in[1];
    const float* tmat = (const float*)d_in[2];
    float*       out  = (float*)d_out;

    void* offp = nullptr;
    cudaGetSymbolAddress(&offp, d_offmin);

    // 0x7F7F7F7F > any possible coordinate -> valid "infinity" for atomicMin
    cudaMemsetAsync(offp, 0x7F, sizeof(int) * BATCH * 2, 0);
    cudaMemsetAsync(d_out, 0, (size_t)out_size * sizeof(float), 0);

    const dim3 grid(BATCH * BLKS_PER_BATCH);  // 2048 blocks, 256 threads
    k_compute<<<grid, 256>>>(pc1, tmat);
    k_scatter<<<grid, 256>>>(feat, out);
}

// round 2
// speedup vs baseline: 1.0830x; 1.0830x over previous
#include <cuda_runtime.h>

// Problem constants (fixed by the reference)
#define BATCH 64
#define NPTS  8192
#define SGRID 384
#define OUTD  128
#define BLKS_PER_BATCH (NPTS / 256)   // 32

// Scratch (static __device__ arrays — no allocations allowed)
__device__ int      d_offmin[BATCH * 2];        // per-batch min of coord (2 dims)
__device__ unsigned d_gpack [BATCH * NPTS];     // packed (g0+1024)|(g1+1024)<<16

// ---------------------------------------------------------------------------
// Kernel 1: per-point lattice math, per-batch coordinate-min reduction,
// store packed greedy coords for the scatter pass.
// ---------------------------------------------------------------------------
__global__ void __launch_bounds__(256) k_compute(const float* __restrict__ pc1,
                                                 const float* __restrict__ tmat)
{
    const int b = blockIdx.x >> 5;                       // 32 blocks per batch
    const int n = ((blockIdx.x & 31) << 8) + threadIdx.x;

    __shared__ float M[9];
    if (threadIdx.x < 9) M[threadIdx.x] = tmat[b * 9 + threadIdx.x];
    __syncthreads();

    const float* p = pc1 + (size_t)b * 3 * NPTS + n;
    const float p0 = p[0], p1 = p[NPTS], p2 = p[2 * NPTS];

    // elevated = M @ p
    const float e0 = M[0] * p0 + M[1] * p1 + M[2] * p2;
    const float e1 = M[3] * p0 + M[4] * p1 + M[5] * p2;
    const float e2 = M[6] * p0 + M[7] * p1 + M[8] * p2;

    // greedy = round(e/3)*3  (IEEE divide + round-half-even, matching jnp)
    const float q0 = rintf(__fdiv_rn(e0, 3.0f));
    const float q1 = rintf(__fdiv_rn(e1, 3.0f));
    const float q2 = rintf(__fdiv_rn(e2, 3.0f));
    const float d0 = e0 - 3.0f * q0;
    const float d1 = e1 - 3.0f * q1;
    const float d2 = e2 - 3.0f * q2;

    const int i0 = (int)q0, i1 = (int)q1, i2 = (int)q2;
    const int rs = i0 + i1 + i2;                // remainder_sum (exact int)

    // rank = inverse of stable descending argsort of (d0,d1,d2)
    int rk0 = (d1 > d0) + (d2 > d0);
    int rk1 = (d0 > d1) + (d2 > d1) + (d0 == d1);
    // rk2 never feeds coords 0/1; not needed downstream.

    int g0 = 3 * i0;
    int g1 = 3 * i1;

    int sh0 = 0, sh1 = 0;
    if (rs > 0) {
        const int thr = 3 - rs;
        sh0 = (rk0 >= thr) ? -3 : 0;
        sh1 = (rk1 >= thr) ? -3 : 0;
    } else if (rs < 0) {
        sh0 = (rk0 < -rs) ? 3 : 0;
        sh1 = (rk1 < -rs) ? 3 : 0;
    }
    g0 += sh0;  g1 += sh1;
    rk0 += sh0 + rs;
    rk1 += sh1 + rs;

    // JAX gather semantics for CANONICAL[rank]: wrap negatives by +3, clamp [0,2]
    int cr0 = (rk0 < 0) ? rk0 + 3 : rk0;  cr0 = min(max(cr0, 0), 2);
    int cr1 = (rk1 < 0) ? rk1 + 3 : rk1;  cr1 = min(max(cr1, 0), 2);

    // min over r of CANONICAL[cr][r] == -cr  => per-point coord min candidate
    int m0 = g0 - cr0;
    int m1 = g1 - cr1;

    d_gpack[b * NPTS + n] = (unsigned)(g0 + 1024) | ((unsigned)(g1 + 1024) << 16);

    // block min-reduction -> 1 atomicMin per coord per block
    #pragma unroll
    for (int o = 16; o; o >>= 1) {
        m0 = min(m0, __shfl_xor_sync(0xFFFFFFFFu, m0, o));
        m1 = min(m1, __shfl_xor_sync(0xFFFFFFFFu, m1, o));
    }
    __shared__ int s0[8], s1[8];
    if ((threadIdx.x & 31) == 0) {
        s0[threadIdx.x >> 5] = m0;
        s1[threadIdx.x >> 5] = m1;
    }
    __syncthreads();
    if (threadIdx.x == 0) {
        int a = s0[0], c = s1[0];
        #pragma unroll
        for (int w = 1; w < 8; w++) { a = min(a, s0[w]); c = min(c, s1[w]); }
        atomicMin(&d_offmin[b * 2 + 0], a);
        atomicMin(&d_offmin[b * 2 + 1], c);
    }
}

// ---------------------------------------------------------------------------
// Kernel 2: scatter-add features into the 128x128x3 output.
// The r=0 simplex coord is exactly greedy (multiple of 3), so after offset
// subtraction it lands on the picked sub-grid: out cell = (row/3, col/3).
// ---------------------------------------------------------------------------
__global__ void __launch_bounds__(256) k_scatter(const float* __restrict__ feat,
                                                 float* __restrict__ out)
{
    const int b = blockIdx.x >> 5;
    const int n = ((blockIdx.x & 31) << 8) + threadIdx.x;

    const unsigned pk = d_gpack[b * NPTS + n];
    const int g0 = (int)(pk & 0xFFFFu) - 1024;
    const int g1 = (int)(pk >> 16)     - 1024;

    const int off0 = __ldg(&d_offmin[b * 2 + 0]);
    const int off1 = __ldg(&d_offmin[b * 2 + 1]);

    const int row = g0 - off0;          // >= 0 by construction (offset is min)
    const int col = g1 - off1;
    if (row < SGRID && col < SGRID) {
        const int u = row / 3;          // row ≡ pts_pick0 (mod 3) exactly
        const int v = col / 3;
        const float* f = feat + (size_t)b * 3 * NPTS + n;
        float* o = out + (((size_t)(b * OUTD + u) * OUTD + v) * 3);
        atomicAdd(o + 0, f[0]);
        atomicAdd(o + 1, f[NPTS]);
        atomicAdd(o + 2, f[2 * NPTS]);
    }
}

// ---------------------------------------------------------------------------
extern "C" void kernel_launch(void* const* d_in, const int* in_sizes, int n_in,
                              void* d_out, int out_size)
{
    const float* pc1  = (const float*)d_in[0];
    const float* feat = (const float*)d_in[1];
    const float* tmat = (const float*)d_in[2];
    float*       out  = (float*)d_out;

    void* offp = nullptr;
    cudaGetSymbolAddress(&offp, d_offmin);

    // 0x7F7F7F7F > any possible coordinate -> valid "infinity" for atomicMin
    cudaMemsetAsync(offp, 0x7F, sizeof(int) * BATCH * 2, 0);
    cudaMemsetAsync(d_out, 0, (size_t)out_size * sizeof(float), 0);

    const dim3 grid(BATCH * BLKS_PER_BATCH);  // 2048 blocks, 256 threads
    k_compute<<<grid, 256>>>(pc1, tmat);
    k_scatter<<<grid, 256>>>(feat, out);
}

// round 4
// speedup vs baseline: 1.3319x; 1.2298x over previous
#include <cuda_runtime.h>

#define BATCH 64
#define NPTS  8192
#define SGRID 384
#define OUTD  128
// 2048 blocks total, 32 per batch, 256 threads.
// out = 64*128*128*3 floats = 3,145,728 floats = 786,432 float4.
#define OUT_F4   786432
#define NTHREADS (2048 * 256)   // 524288

__device__ int2     d_blockmin[BATCH * 32];     // per-block coord minima
__device__ unsigned d_gpack  [BATCH * NPTS];    // packed (g0+1024)|(g1+1024)<<16

// Vector float2 reduction (no return) — sm_90+; needs 8B-aligned address.
__device__ __forceinline__ void red_add_v2f32(float* p, float a, float b) {
    asm volatile("red.global.add.v2.f32 [%0], {%1, %2};"
                 :: "l"(p), "f"(a), "f"(b) : "memory");
}

// ---------------------------------------------------------------------------
// Kernel 1: zero the output (grid-stride), per-point lattice math,
// per-block coordinate min.
// ---------------------------------------------------------------------------
__global__ void __launch_bounds__(256) k_compute(const float* __restrict__ pc1,
                                                 const float* __restrict__ tmat,
                                                 float* __restrict__ out)
{
    // ---- zero-fill d_out: 786432 float4 over 524288 threads (1.5 each) ----
    {
        const int gid = blockIdx.x * 256 + threadIdx.x;
        float4 z = make_float4(0.f, 0.f, 0.f, 0.f);
        float4* o4 = reinterpret_cast<float4*>(out);
        o4[gid] = z;                                  // [0, 524288)
        if (gid < OUT_F4 - NTHREADS) o4[NTHREADS + gid] = z;  // [524288, 786432)
    }

    const int b = blockIdx.x >> 5;
    const int n = ((blockIdx.x & 31) << 8) + threadIdx.x;

    __shared__ float M[9];
    if (threadIdx.x < 9) M[threadIdx.x] = tmat[b * 9 + threadIdx.x];
    __syncthreads();

    const float* p = pc1 + (size_t)b * 3 * NPTS + n;
    const float p0 = p[0], p1 = p[NPTS], p2 = p[2 * NPTS];

    const float e0 = M[0] * p0 + M[1] * p1 + M[2] * p2;
    const float e1 = M[3] * p0 + M[4] * p1 + M[5] * p2;
    const float e2 = M[6] * p0 + M[7] * p1 + M[8] * p2;

    // greedy = round(e/3)*3 (IEEE div + round-half-even, matching jnp)
    const float q0 = rintf(__fdiv_rn(e0, 3.0f));
    const float q1 = rintf(__fdiv_rn(e1, 3.0f));
    const float q2 = rintf(__fdiv_rn(e2, 3.0f));
    const float d0 = e0 - 3.0f * q0;
    const float d1 = e1 - 3.0f * q1;
    const float d2 = e2 - 3.0f * q2;

    const int i0 = (int)q0, i1 = (int)q1, i2 = (int)q2;
    const int rs = i0 + i1 + i2;   // remainder_sum (exact)

    // rank = inverse of stable descending argsort of (d0,d1,d2)
    int rk0 = (d1 > d0) + (d2 > d0);
    int rk1 = (d0 > d1) + (d2 > d1) + (d0 == d1);

    int g0 = 3 * i0;
    int g1 = 3 * i1;

    int sh0 = 0, sh1 = 0;
    if (rs > 0) {
        const int thr = 3 - rs;
        sh0 = (rk0 >= thr) ? -3 : 0;
        sh1 = (rk1 >= thr) ? -3 : 0;
    } else if (rs < 0) {
        sh0 = (rk0 < -rs) ? 3 : 0;
        sh1 = (rk1 < -rs) ? 3 : 0;
    }
    g0 += sh0;  g1 += sh1;
    rk0 += sh0 + rs;
    rk1 += sh1 + rs;

    // JAX gather semantics for CANONICAL[rank]: wrap negatives by +3, clamp [0,2]
    int cr0 = (rk0 < 0) ? rk0 + 3 : rk0;  cr0 = min(max(cr0, 0), 2);
    int cr1 = (rk1 < 0) ? rk1 + 3 : rk1;  cr1 = min(max(cr1, 0), 2);

    int m0 = g0 - cr0;   // per-point coord-min candidate (min_r canonical = -cr)
    int m1 = g1 - cr1;

    d_gpack[b * NPTS + n] = (unsigned)(g0 + 1024) | ((unsigned)(g1 + 1024) << 16);

    // block min-reduction -> single int2 store (no atomics, no init needed)
    #pragma unroll
    for (int o = 16; o; o >>= 1) {
        m0 = min(m0, __shfl_xor_sync(0xFFFFFFFFu, m0, o));
        m1 = min(m1, __shfl_xor_sync(0xFFFFFFFFu, m1, o));
    }
    __shared__ int s0[8], s1[8];
    if ((threadIdx.x & 31) == 0) {
        s0[threadIdx.x >> 5] = m0;
        s1[threadIdx.x >> 5] = m1;
    }
    __syncthreads();
    if (threadIdx.x == 0) {
        int a = s0[0], c = s1[0];
        #pragma unroll
        for (int w = 1; w < 8; w++) { a = min(a, s0[w]); c = min(c, s1[w]); }
        d_blockmin[blockIdx.x] = make_int2(a, c);
    }
}

// ---------------------------------------------------------------------------
// Kernel 2: reduce 32 block-minima -> batch offset, then scatter-add features
// with 2 reduction ops per point (v2 + scalar, parity-aligned).
// ---------------------------------------------------------------------------
__global__ void __launch_bounds__(256) k_scatter(const float* __restrict__ feat,
                                                 float* __restrict__ out)
{
    const int b = blockIdx.x >> 5;
    const int n = ((blockIdx.x & 31) << 8) + threadIdx.x;

    __shared__ int soff0, soff1;
    if (threadIdx.x < 32) {
        int2 v = d_blockmin[b * 32 + threadIdx.x];
        int a = v.x, c = v.y;
        #pragma unroll
        for (int o = 16; o; o >>= 1) {
            a = min(a, __shfl_xor_sync(0xFFFFFFFFu, a, o));
            c = min(c, __shfl_xor_sync(0xFFFFFFFFu, c, o));
        }
        if (threadIdx.x == 0) { soff0 = a; soff1 = c; }
    }

    const unsigned pk = d_gpack[b * NPTS + n];
    const int g0 = (int)(pk & 0xFFFFu) - 1024;
    const int g1 = (int)(pk >> 16)     - 1024;

    const float* f = feat + (size_t)b * 3 * NPTS + n;
    const float f0 = f[0], f1 = f[NPTS], f2 = f[2 * NPTS];

    __syncthreads();
    const int row = g0 - soff0;     // >= 0 (offset is the min)
    const int col = g1 - soff1;

    if (row < SGRID && col < SGRID) {
        const int u = row / 3;      // row ≡ pts_pick0 (mod 3) exactly
        const int v = col / 3;
        const int idx = (b * OUTD + u) * OUTD + v;
        float* o = out + (size_t)idx * 3;

        // cell byte base = 12*idx: even idx -> &o[0] is 8-aligned;
        // odd idx -> &o[1] is 8-aligned. Always one v2 + one scalar red.
        const int odd = idx & 1;
        red_add_v2f32(o + odd, odd ? f1 : f0, odd ? f2 : f1);
        atomicAdd(o + (odd ? 0 : 2), odd ? f0 : f2);
    }
}

// ---------------------------------------------------------------------------
extern "C" void kernel_launch(void* const* d_in, const int* in_sizes, int n_in,
                              void* d_out, int out_size)
{
    const float* pc1  = (const float*)d_in[0];
    const float* feat = (const float*)d_in[1];
    const float* tmat = (const float*)d_in[2];
    float*       out  = (float*)d_out;

    const dim3 grid(BATCH * 32);   // 2048 blocks
    k_compute<<<grid, 256>>>(pc1, tmat, out);
    k_scatter<<<grid, 256>>>(feat, out);
}